// round 8
// baseline (speedup 1.0000x reference)
#include <cuda_runtime.h>
#include <cuda_fp16.h>
#include <cstdint>

// ---------------------------------------------------------------------------
// SparseGaussianHead: two sparse-conv layers (27-offset gather-GEMM) + GELU
//   L1: [400k x 64] -> [400k x 38]   (N padded to 40)
//   L2: [400k x 38] -> [400k x 38]   (K padded to 48, N padded to 40)
// fp16 m16n8k16 MMA, fp32 accumulate.
// R6: 256 rows/CTA (64 rows/warp -> B-fragment reuse x4), dirty-tracked A tile
//     (invalid rows rewritten only on state change), single sync pair.
// ---------------------------------------------------------------------------

#define NPTS 400000
#define NOFF 27

__device__ __half g_feat[NPTS * 64];          // features, fp16
__device__ __half g_h[NPTS * 48];             // gelu out, cols 38..47 = 0
__device__ __half g_W1t[NOFF * 40 * 72];      // W1^T [k][n][c], stride 72 halves
__device__ __half g_W2t[NOFF * 40 * 56];      // W2^T [k][n][c], stride 56 halves

__device__ __forceinline__ float gelu_exact(float x) {
    return 0.5f * x * (1.0f + erff(x * 0.7071067811865476f));
}

// ------------------------------ prep kernels ------------------------------

__global__ void prep_feat(const float* __restrict__ F) {
    int e = blockIdx.x * 256 + threadIdx.x;   // NPTS*64 exact multiple of 256
    g_feat[e] = __float2half_rn(F[e]);
}

__global__ void prep_w1(const float* __restrict__ W1) {
    int e = blockIdx.x * 256 + threadIdx.x;
    if (e >= NOFF * 40 * 64) return;
    int c = e & 63;               // input channel (K dim)
    int n = (e >> 6) % 40;        // output channel
    int k = e / (64 * 40);
    float v = (n < 38) ? W1[(k * 64 + c) * 38 + n] : 0.0f;
    g_W1t[k * (40 * 72) + n * 72 + c] = __float2half_rn(v);
}

__global__ void prep_w2(const float* __restrict__ W2) {
    int e = blockIdx.x * 256 + threadIdx.x;
    if (e >= NOFF * 40 * 48) return;
    int c = e % 48;
    int rest = e / 48;
    int n = rest % 40;
    int k = rest / 40;
    float v = (n < 38 && c < 38) ? W2[(k * 38 + c) * 38 + n] : 0.0f;
    g_W2t[k * (40 * 56) + n * 56 + c] = __float2half_rn(v);
}

// ------------------------------ conv kernel -------------------------------
// 128 threads = 4 warps; CTA tile 256 rows x 40 cols; warp w owns rows
// 64w..64w+63 (four m16 tiles, B fragments reused 4x). Thread tid gathers
// local rows tid and tid+128 (row==lane store pattern: conflict-free phases).
// MODE 0: in g_feat, out g_h (exact GELU, fp16, cols 40..47 zeroed)
// MODE 1: in g_h,    out d_out (first 38 cols, fp32)

template <int KD, int MODE>
__global__ __launch_bounds__(128) void conv_k(const int* __restrict__ nbr,
                                              float* __restrict__ dout) {
    constexpr int AS   = (KD == 64) ? 72 : 56;  // halves per A/W row (16B mult)
    constexpr int CHK  = KD / 8;                // 16B chunks per A row (8 / 6)
    constexpr int KK   = KD / 16;               // K-steps (4 / 3)
    constexpr int WCHK = 5 * AS;                // 16B chunks in W tile

    __shared__ __half As[256 * AS];
    __shared__ __half Ws[40 * AS];

    const __half* __restrict__ feat = (MODE == 0) ? g_feat : g_h;
    const __half* __restrict__ Wg   = (MODE == 0) ? g_W1t  : g_W2t;

    const int tid  = threadIdx.x;
    const int warp = tid >> 5;
    const int lane = tid & 31;
    const int g    = lane >> 2;   // 0..7
    const int t    = lane & 3;    // 0..3
    const int base = blockIdx.x * 256;

    const unsigned as_base = (unsigned)__cvta_generic_to_shared(As);
    const unsigned ws_base = (unsigned)__cvta_generic_to_shared(Ws);

    float acc[4][5][4];
#pragma unroll
    for (int tt = 0; tt < 4; tt++)
#pragma unroll
        for (int j = 0; j < 5; j++)
#pragma unroll
            for (int q = 0; q < 4; q++) acc[tt][j][q] = 0.0f;

    // zero both owned rows once; afterwards rewrite only on state change
    {
        const float4 z = make_float4(0.f, 0.f, 0.f, 0.f);
#pragma unroll
        for (int m = 0; m < CHK; m++) {
            *(float4*)&As[(size_t)tid * AS + 8 * m]         = z;
            *(float4*)&As[(size_t)(tid + 128) * AS + 8 * m] = z;
        }
    }
    bool dirty0 = false, dirty1 = false;

    for (int k = 0; k < NOFF; k++) {
        __syncthreads();   // previous iteration's MMAs done reading smem

        // --- gather row tid ---
        {
            const int grow = base + tid;
            int idx = NPTS;
            if (grow < NPTS) idx = __ldg(&nbr[k * NPTS + grow]);
            const bool valid = (unsigned)idx < (unsigned)NPTS;
            if (valid) {
                const char* src = (const char*)(feat + (size_t)idx * KD);
                const unsigned dst = as_base + (unsigned)(tid * AS) * 2u;
#pragma unroll
                for (int m = 0; m < CHK; m++)
                    asm volatile("cp.async.ca.shared.global [%0], [%1], 16;"
                                 :: "r"(dst + (unsigned)(16 * m)),
                                    "l"(src + 16 * m));
            } else if (dirty0) {
                const float4 z = make_float4(0.f, 0.f, 0.f, 0.f);
#pragma unroll
                for (int m = 0; m < CHK; m++)
                    *(float4*)&As[(size_t)tid * AS + 8 * m] = z;
            }
            dirty0 = valid;
        }
        // --- gather row tid + 128 ---
        {
            const int grow = base + tid + 128;
            int idx = NPTS;
            if (grow < NPTS) idx = __ldg(&nbr[k * NPTS + grow]);
            const bool valid = (unsigned)idx < (unsigned)NPTS;
            if (valid) {
                const char* src = (const char*)(feat + (size_t)idx * KD);
                const unsigned dst = as_base + (unsigned)((tid + 128) * AS) * 2u;
#pragma unroll
                for (int m = 0; m < CHK; m++)
                    asm volatile("cp.async.ca.shared.global [%0], [%1], 16;"
                                 :: "r"(dst + (unsigned)(16 * m)),
                                    "l"(src + 16 * m));
            } else if (dirty1) {
                const float4 z = make_float4(0.f, 0.f, 0.f, 0.f);
#pragma unroll
                for (int m = 0; m < CHK; m++)
                    *(float4*)&As[(size_t)(tid + 128) * AS + 8 * m] = z;
            }
            dirty1 = valid;
        }
        // --- W tile: flat copy of pre-transposed image (40 x AS halves) ---
        {
            const char* wsrc = (const char*)(Wg + (size_t)k * 40 * AS);
#pragma unroll
            for (int e = tid; e < WCHK; e += 128)
                asm volatile("cp.async.ca.shared.global [%0], [%1], 16;"
                             :: "r"(ws_base + (unsigned)(16 * e)),
                                "l"(wsrc + 16 * e));
        }
        asm volatile("cp.async.commit_group;" ::: "memory");
        asm volatile("cp.async.wait_group 0;" ::: "memory");
        __syncthreads();

        // --- MMA: [256 x KD] @ [KD x 40]; warp w rows 64w..64w+63 ---
#pragma unroll
        for (int kk = 0; kk < KK; ++kk) {
            const int kc = kk * 16 + 2 * t;
            unsigned a[4][4];
#pragma unroll
            for (int tt = 0; tt < 4; tt++) {
                const int r = warp * 64 + tt * 16 + g;
                a[tt][0] = *(const unsigned*)&As[r * AS + kc];
                a[tt][1] = *(const unsigned*)&As[(r + 8) * AS + kc];
                a[tt][2] = *(const unsigned*)&As[r * AS + kc + 8];
                a[tt][3] = *(const unsigned*)&As[(r + 8) * AS + kc + 8];
            }
#pragma unroll
            for (int j = 0; j < 5; j++) {
                const unsigned b0 = *(const unsigned*)&Ws[(j * 8 + g) * AS + kc];
                const unsigned b1 = *(const unsigned*)&Ws[(j * 8 + g) * AS + kc + 8];
#pragma unroll
                for (int tt = 0; tt < 4; tt++) {
                    asm volatile(
                        "mma.sync.aligned.m16n8k16.row.col.f32.f16.f16.f32 "
                        "{%0,%1,%2,%3}, {%4,%5,%6,%7}, {%8,%9}, {%0,%1,%2,%3};\n"
                        : "+f"(acc[tt][j][0]), "+f"(acc[tt][j][1]),
                          "+f"(acc[tt][j][2]), "+f"(acc[tt][j][3])
                        : "r"(a[tt][0]), "r"(a[tt][1]), "r"(a[tt][2]),
                          "r"(a[tt][3]), "r"(b0), "r"(b1));
                }
            }
        }
    }

    // --- epilogue (guard ragged last CTA) ---
#pragma unroll
    for (int tt = 0; tt < 4; tt++) {
        const int r0 = base + warp * 64 + tt * 16 + g;
#pragma unroll
        for (int j = 0; j < 5; j++) {
            const int c0 = j * 8 + 2 * t;
            if (MODE == 0) {
                if (r0 < NPTS) {
                    __half2* h0 = (__half2*)&g_h[(size_t)r0 * 48 + c0];
                    *h0 = __floats2half2_rn(gelu_exact(acc[tt][j][0]),
                                            gelu_exact(acc[tt][j][1]));
                }
                if (r0 + 8 < NPTS) {
                    __half2* h1 = (__half2*)&g_h[(size_t)(r0 + 8) * 48 + c0];
                    *h1 = __floats2half2_rn(gelu_exact(acc[tt][j][2]),
                                            gelu_exact(acc[tt][j][3]));
                }
            } else {
                if (r0 < NPTS) {
                    if (c0 < 38)     dout[(size_t)r0 * 38 + c0]     = acc[tt][j][0];
                    if (c0 + 1 < 38) dout[(size_t)r0 * 38 + c0 + 1] = acc[tt][j][1];
                }
                if (r0 + 8 < NPTS) {
                    if (c0 < 38)     dout[(size_t)(r0 + 8) * 38 + c0]     = acc[tt][j][2];
                    if (c0 + 1 < 38) dout[(size_t)(r0 + 8) * 38 + c0 + 1] = acc[tt][j][3];
                }
            }
        }
        if (MODE == 0 && t == 0) {   // zero pad cols 40..47
            const float4 z = make_float4(0.f, 0.f, 0.f, 0.f);
            if (r0 < NPTS)     *(float4*)&g_h[(size_t)r0 * 48 + 40]       = z;
            if (r0 + 8 < NPTS) *(float4*)&g_h[(size_t)(r0 + 8) * 48 + 40] = z;
        }
    }
}

// ------------------------------ launch ------------------------------------

extern "C" void kernel_launch(void* const* d_in, const int* in_sizes, int n_in,
                              void* d_out, int out_size) {
    const float* F   = (const float*)d_in[0];   // [400000, 64]
    const int*   nbr = (const int*)d_in[1];     // [27, 400000]
    const float* W1  = (const float*)d_in[2];   // [27, 64, 38]
    const float* W2  = (const float*)d_in[3];   // [27, 38, 38]
    float* out = (float*)d_out;                 // [400000, 38]

    prep_feat<<<(NPTS * 64) / 256, 256>>>(F);
    prep_w1<<<(NOFF * 40 * 64 + 255) / 256, 256>>>(W1);
    prep_w2<<<(NOFF * 40 * 48 + 255) / 256, 256>>>(W2);

    const int grid = (NPTS + 255) / 256;        // 1563 (last CTA ragged)
    conv_k<64, 0><<<grid, 128>>>(nbr, nullptr); // L1 + GELU -> g_h
    conv_k<48, 1><<<grid, 128>>>(nbr, out);     // L2 -> d_out
}